// round 10
// baseline (speedup 1.0000x reference)
#include <cuda_runtime.h>
#include <cuda_fp16.h>
#include <cstdint>
#include <math.h>

#define N_NODES 10000
#define N_EDGES 160000
#define F_DIM   64
#define NHEAD   4
#define N_PAD   10048                  // N rounded up to 64

// ---------------- scratch (device globals) ----------------------------------
__device__ uint2   g_radh[N_NODES * 64];   // fp16 radial feats, node-major 256/node
__device__ uint2   g_tanh_[N_NODES * 64];  // fp16 tangential feats
__device__ float4  g_score_r[N_NODES];     // per-node logit scalars (4 heads)
__device__ float4  g_score_t[N_NODES];
__device__ float   g_vr[NHEAD * F_DIM];    // w_proj @ radial_score
__device__ float   g_vt[NHEAD * F_DIM];
__device__ float4  g_rexp[N_EDGES];        // exp(radial logit), sorted slot
__device__ float4  g_texp[N_EDGES];        // exp(tangential logit)
__device__ float   g_scale;
__device__ float   g_tconst[2 * NHEAD];    // tbias, tweight
__device__ int     g_indeg[N_NODES];
__device__ int     g_offs[N_NODES];
__device__ int     g_cursor[N_NODES];
__device__ int     g_se[N_EDGES];          // sorted-by-receiver sender id
__device__ int     g_alloc;
__device__ uint32_t g_wt[8 * 64 * 64];     // pre-converted tf32 weights [bc][f][g]
__device__ uint4   g_xt[N_PAD * 16];       // pre-converted tf32 x [n][f], padded

__device__ __forceinline__ float softplusf(float z) {
    return z > 20.f ? z : log1pf(__expf(z));
}

__device__ __forceinline__ uint32_t f2tf32(float v) {
    uint32_t u;
    asm("cvt.rna.tf32.f32 %0, %1;" : "=r"(u) : "f"(v));
    return u;
}

__device__ __forceinline__ void mma_tf32(float4& c,
                                         uint32_t a0, uint32_t a1, uint32_t a2, uint32_t a3,
                                         uint32_t b0, uint32_t b1) {
    asm volatile(
        "mma.sync.aligned.m16n8k8.row.col.f32.tf32.tf32.f32 "
        "{%0,%1,%2,%3}, {%4,%5,%6,%7}, {%8,%9}, {%0,%1,%2,%3};"
        : "+f"(c.x), "+f"(c.y), "+f"(c.z), "+f"(c.w)
        : "r"(a0), "r"(a1), "r"(a2), "r"(a3), "r"(b0), "r"(b1));
}

// ---------------- K0: fold vectors + zero hist + tf32 conversions -----------
// grid 640 x 256.
__global__ void k_prep(const float* __restrict__ x,
                       const float* __restrict__ wproj,
                       const float* __restrict__ rW,
                       const float* __restrict__ tW,
                       const float* __restrict__ rs,
                       const float* __restrict__ ts,
                       const float* __restrict__ rdls,
                       const float* __restrict__ tbias,
                       const float* __restrict__ tweight) {
    int i = blockIdx.x * blockDim.x + threadIdx.x;
    int stride = gridDim.x * blockDim.x;

    for (int j = i; j < N_NODES; j += stride) g_indeg[j] = 0;
    if (i == 0) g_alloc = 0;

    // x -> tf32 (padded tail left zero / previously written values are valid)
    uint32_t* xt = (uint32_t*)g_xt;
    for (int j = i; j < N_NODES * F_DIM; j += stride) xt[j] = f2tf32(x[j]);

    // weights -> tf32: idx = bc*4096 + f*64 + g
    if (i < 8 * 4096) {
        int bc = i >> 12, within = i & 4095;
        const float* src = (bc < 4) ? (rW + bc * 4096) : (tW + (bc - 4) * 4096);
        g_wt[i] = f2tf32(src[within]);
    }

    if (blockIdx.x != 0) return;
    int t = threadIdx.x;               // 0..255 -> (h,f)
    int h = t >> 6, f = t & 63;
    const float* W  = wproj + h * F_DIM * F_DIM + f * F_DIM;
    const float* rv = rs + h * F_DIM;
    const float* tv = ts + h * F_DIM;
    float ar = 0.f, at = 0.f;
#pragma unroll
    for (int g = 0; g < F_DIM; g++) { ar += W[g] * rv[g]; at += W[g] * tv[g]; }
    g_vr[t] = ar;
    g_vt[t] = at;
    if (t == 0) g_scale = softplusf(rdls[0]);
    if (t < NHEAD)          g_tconst[t] = tbias[t];
    else if (t < 2 * NHEAD) g_tconst[t] = tweight[t - NHEAD];
}

// ---------------- K1: in-degree histogram ------------------------------------
__global__ void k_hist(const int* __restrict__ eidx) {
    int e = blockIdx.x * blockDim.x + threadIdx.x;
    if (e < N_EDGES) atomicAdd(&g_indeg[eidx[N_EDGES + e]], 1);
}

// ---------------- K2: parallel range allocation ------------------------------
__global__ void k_base() {
    int n = blockIdx.x * blockDim.x + threadIdx.x;
    if (n < N_NODES) {
        int base = atomicAdd(&g_alloc, g_indeg[n]);
        g_offs[n]   = base;
        g_cursor[n] = base;
    }
}

// ---------------- K3: tensor-core projection GEMM + balanced fused scores ---
// grid (ceil(N/64), 8): blockIdx.y = bc (col group). Single pass per block.
// x and weights pre-converted tf32; block bc computes score pairs [bc*64,+64).
#define XS_STRIDE 68
#define WS_STRIDE 72
__global__ void __launch_bounds__(256) k_node_mma() {
    __shared__ uint32_t xs[64 * XS_STRIDE];
    __shared__ uint32_t ws[64 * WS_STRIDE];
    int t  = threadIdx.x;
    int n0 = blockIdx.x * 64;
    int bc = blockIdx.y;                       // 0..7

    // stage x tile (already tf32): 1024 uint4, 4 per thread
    const uint4* xsrc = g_xt + n0 * 16;
#pragma unroll
    for (int i = 0; i < 4; i++) {
        int idx4 = i * 256 + t;                // 0..1023
        int n = idx4 >> 4, gq = idx4 & 15;
        uint4 v = xsrc[idx4];
        *(uint4*)(xs + n * XS_STRIDE + gq * 4) = v;
    }
    // stage weight tile (already tf32): 4 uint4 per thread
    const uint32_t* wsrc = g_wt + bc * 4096;
#pragma unroll
    for (int i = 0; i < 4; i++) {
        int idx4 = i * 256 + t;
        int f = idx4 >> 4, gq = idx4 & 15;
        uint4 v = ((const uint4*)wsrc)[idx4];
        *(uint4*)(ws + f * WS_STRIDE + gq * 4) = v;
    }
    __syncthreads();

    // balanced fused scores: this block handles pair idx in [bc*64, bc*64+64)
    if (t < 64) {
        int idx = bc * 64 + t;                 // 0..511 across the 8 bc slices
        int nl = idx >> 3, sub = idx & 7;
        int hh = sub & 3;
        bool isR = sub < 4;
        if (n0 + nl < N_NODES) {
            const float* v = (isR ? g_vr : g_vt) + hh * F_DIM;
            const uint32_t* xrow = xs + nl * XS_STRIDE;
            float s = 0.f;
#pragma unroll
            for (int f = 0; f < F_DIM; f++) s += __uint_as_float(xrow[f]) * v[f];
            float* dst = isR ? (float*)g_score_r : (float*)g_score_t;
            dst[(n0 + nl) * NHEAD + hh] = s;
        }
    }

    int w = t >> 5, lane = t & 31;
    int g4 = lane >> 2, tig = lane & 3;
    int nt = w & 3;                  // node strip (16 nodes)
    int cb = (w >> 2) * 4;           // first of 4 col tiles (8 cols each)
    const uint32_t* xrow0 = xs + (nt * 16 + g4) * XS_STRIDE;
    const uint32_t* xrow1 = xrow0 + 8 * XS_STRIDE;

    float4 acc[4];
#pragma unroll
    for (int ct = 0; ct < 4; ct++) acc[ct] = make_float4(0.f, 0.f, 0.f, 0.f);
#pragma unroll
    for (int k0 = 0; k0 < 64; k0 += 8) {
        uint32_t a0 = xrow0[k0 + tig];
        uint32_t a1 = xrow1[k0 + tig];
        uint32_t a2 = xrow0[k0 + tig + 4];
        uint32_t a3 = xrow1[k0 + tig + 4];
#pragma unroll
        for (int ct = 0; ct < 4; ct++) {
            int gcol = (cb + ct) * 8 + g4;
            uint32_t b0 = ws[(k0 + tig) * WS_STRIDE + gcol];
            uint32_t b1 = ws[(k0 + tig + 4) * WS_STRIDE + gcol];
            mma_tf32(acc[ct], a0, a1, a2, a3, b0, b1);
        }
    }

    // epilogue: fp16 store, node-major [n][256]
    __half* dst = (bc < 4) ? (__half*)g_radh : (__half*)g_tanh_;
    int cbase = (bc & 3) * 64;
    int n_a = n0 + nt * 16 + g4;
    int n_b = n_a + 8;
#pragma unroll
    for (int ct = 0; ct < 4; ct++) {
        int c = cbase + (cb + ct) * 8 + tig * 2;
        __half2 h01 = __floats2half2_rn(acc[ct].x, acc[ct].y);
        __half2 h23 = __floats2half2_rn(acc[ct].z, acc[ct].w);
        if (n_a < N_NODES) *(__half2*)(dst + n_a * 256 + c) = h01;
        if (n_b < N_NODES) *(__half2*)(dst + n_b * 256 + c) = h23;
    }
}

// ---------------- K4: edge logits -> exp, scattered into sorted slots -------
__global__ void k_edge(const int* __restrict__ eidx,
                       const float* __restrict__ elen) {
    int e = blockIdx.x * blockDim.x + threadIdx.x;
    if (e >= N_EDGES) return;
    int s = eidx[e];
    int r = eidx[N_EDGES + e];
    float len = elen[e];

    float4 srs = g_score_r[s], srr = g_score_r[r];
    float4 sts = g_score_t[s], str = g_score_t[r];

    float it0 = 1.f / (softplusf(g_tconst[0] + g_tconst[4] * len) + 1e-4f);
    float it1 = 1.f / (softplusf(g_tconst[1] + g_tconst[5] * len) + 1e-4f);
    float it2 = 1.f / (softplusf(g_tconst[2] + g_tconst[6] * len) + 1e-4f);
    float it3 = 1.f / (softplusf(g_tconst[3] + g_tconst[7] * len) + 1e-4f);
    float sl = g_scale * len;

    float4 re, te;
    re.x = __expf((srs.x - srr.x - sl) * it0);
    re.y = __expf((srs.y - srr.y - sl) * it1);
    re.z = __expf((srs.z - srr.z - sl) * it2);
    re.w = __expf((srs.w - srr.w - sl) * it3);
    te.x = __expf(sts.x - str.x);
    te.y = __expf(sts.y - str.y);
    te.z = __expf(sts.z - str.z);
    te.w = __expf(sts.w - str.w);

    int pos = atomicAdd(&g_cursor[r], 1);
    g_se[pos]   = s;
    g_rexp[pos] = re;
    g_texp[pos] = te;
}

// ---------------- K5: dual-stream gather + normalize + w_out + residual -----
__global__ void __launch_bounds__(64) k_gather(const float* __restrict__ x,
                                               const float* __restrict__ wout,
                                               float* __restrict__ out) {
    __shared__ float4 tmp[64];
    __shared__ float  p[F_DIM];
    int n = blockIdx.x;
    int t = threadIdx.x;
    int h = t >> 4;
    int base = g_offs[n];
    int deg  = g_indeg[n];

    float4 accr = make_float4(0.f, 0.f, 0.f, 0.f);
    float4 acct = make_float4(0.f, 0.f, 0.f, 0.f);
    float sdr = 0.f, sdt = 0.f;

#define GATHER_ONE(J)                                                          \
    {                                                                          \
        int s = g_se[J];                                                       \
        float4 re4 = g_rexp[J];                                                \
        float4 te4 = g_texp[J];                                                \
        float ar = (h < 2) ? (h == 0 ? re4.x : re4.y)                          \
                           : (h == 2 ? re4.z : re4.w);                         \
        float at = (h < 2) ? (h == 0 ? te4.x : te4.y)                          \
                           : (h == 2 ? te4.z : te4.w);                         \
        uint2 rv = g_radh[s * 64 + t];                                         \
        uint2 tv = g_tanh_[s * 64 + t];                                        \
        float2 r0 = __half22float2(*(__half2*)&rv.x);                          \
        float2 r1 = __half22float2(*(__half2*)&rv.y);                          \
        float2 t0 = __half22float2(*(__half2*)&tv.x);                          \
        float2 t1 = __half22float2(*(__half2*)&tv.y);                          \
        accr.x += ar * r0.x; accr.y += ar * r0.y;                              \
        accr.z += ar * r1.x; accr.w += ar * r1.y;                              \
        acct.x += at * t0.x; acct.y += at * t0.y;                              \
        acct.z += at * t1.x; acct.w += at * t1.y;                              \
        sdr += ar; sdt += at;                                                  \
    }

    int half1 = deg >> 1;
    int j1 = base, e1 = base + half1;
    int j2 = e1,   e2 = base + deg;
#pragma unroll 2
    for (; j1 < e1; j1++, j2++) {
        GATHER_ONE(j1);
        GATHER_ONE(j2);
    }
    for (; j2 < e2; j2++) GATHER_ONE(j2);
#undef GATHER_ONE

    float4 res = make_float4(0.f, 0.f, 0.f, 0.f);
    if (deg > 0) {
        float ir = 1.f / sdr;
        float it = 1.f / sdt;
        uint2 rv = g_radh[n * 64 + t];
        uint2 tv = g_tanh_[n * 64 + t];
        float2 r0 = __half22float2(*(__half2*)&rv.x);
        float2 r1 = __half22float2(*(__half2*)&rv.y);
        float2 t0 = __half22float2(*(__half2*)&tv.x);
        float2 t1 = __half22float2(*(__half2*)&tv.y);
        res.x = accr.x * ir + acct.x * it - r0.x - t0.x;
        res.y = accr.y * ir + acct.y * it - r0.y - t0.y;
        res.z = accr.z * ir + acct.z * it - r1.x - t1.x;
        res.w = accr.w * ir + acct.w * it - r1.y - t1.y;
    }
    tmp[t] = res;
    __syncthreads();
    if (t < 16) {
        float4 a = tmp[t], b = tmp[t + 16], c = tmp[t + 32], d = tmp[t + 48];
        p[4 * t + 0] = (a.x + b.x + c.x + d.x) * 0.25f;
        p[4 * t + 1] = (a.y + b.y + c.y + d.y) * 0.25f;
        p[4 * t + 2] = (a.z + b.z + c.z + d.z) * 0.25f;
        p[4 * t + 3] = (a.w + b.w + c.w + d.w) * 0.25f;
    }
    __syncthreads();
    float o = x[n * F_DIM + t];
#pragma unroll
    for (int k = 0; k < F_DIM; k++) o += p[k] * wout[k * F_DIM + t];
    out[n * F_DIM + t] = o;
}

// ---------------- launch -----------------------------------------------------
extern "C" void kernel_launch(void* const* d_in, const int* in_sizes, int n_in,
                              void* d_out, int out_size) {
    const float* x      = (const float*)d_in[0];
    const int*   eidx   = (const int*)d_in[1];
    // d_in[2] = edge_vec : unused by the reference math
    const float* elen   = (const float*)d_in[3];
    const float* wproj  = (const float*)d_in[4];
    const float* rW     = (const float*)d_in[5];
    const float* tW     = (const float*)d_in[6];
    const float* rs     = (const float*)d_in[7];
    const float* ts     = (const float*)d_in[8];
    const float* rdls   = (const float*)d_in[9];
    const float* tbias  = (const float*)d_in[10];
    const float* tweight= (const float*)d_in[11];
    const float* wout   = (const float*)d_in[12];
    float* out = (float*)d_out;

    k_prep<<<640, 256>>>(x, wproj, rW, tW, rs, ts, rdls, tbias, tweight);
    k_hist<<<(N_EDGES + 255) / 256, 256>>>(eidx);
    k_base<<<(N_NODES + 255) / 256, 256>>>();
    dim3 ggrid((N_NODES + 63) / 64, 8);
    k_node_mma<<<ggrid, 256>>>();
    k_edge<<<(N_EDGES + 255) / 256, 256>>>(eidx, elen);
    k_gather<<<N_NODES, 64>>>(x, wout, out);
}